// round 1
// baseline (speedup 1.0000x reference)
#include <cuda_runtime.h>

// ---------------------------------------------------------------------------
// ConvTemporalGraphical: gating MLP (big GEMM K=204800) + softmax expert mix
// + batched graph convolution.
//
// K1: h0 partials = x_flat[32,204800] @ W0[204800,256]   (K-split, f32x2 FMA)
// K2: reduce partials + b0 + ELU + (@W1 + b1) + ELU      (one block per row m)
// K3: logits @ W2 + softmax -> w[32,4]
// K4: AS[n,t] = sum_e w[n,e] A[e,t];  out[n,:,t,:] = x[n,:,t,:] @ AS[n,t]
// ---------------------------------------------------------------------------

#define K_DIM 204800
#define M_DIM 32
#define N_DIM 256
#define SPLIT 400
#define KC    512   // K per block
#define KT    32    // K per smem tile

__device__ float g_partial[SPLIT * M_DIM * N_DIM];  // 13.1 MB scratch
__device__ float g_h1[M_DIM * N_DIM];
__device__ float g_w[M_DIM * 4];

// ---- packed f32x2 helpers (ptxas won't auto-fuse; must come from PTX) -----
__device__ __forceinline__ unsigned long long pack2(float lo, float hi) {
    unsigned long long r;
    asm("mov.b64 %0, {%1, %2};" : "=l"(r) : "f"(lo), "f"(hi));
    return r;
}
__device__ __forceinline__ void unpack2(unsigned long long v, float& lo, float& hi) {
    asm("mov.b64 {%0, %1}, %2;" : "=f"(lo), "=f"(hi) : "l"(v));
}
__device__ __forceinline__ void ffma2(unsigned long long& d, unsigned long long a,
                                      unsigned long long b) {
    asm("fma.rn.f32x2 %0, %1, %2, %0;" : "+l"(d) : "l"(a), "l"(b));
}

__device__ __forceinline__ float elu(float v) {
    return v > 0.0f ? v : expm1f(v);
}

// ---------------------------------------------------------------------------
// K1: big GEMM, K-split. Block s covers k in [s*KC, (s+1)*KC), full 32x256 tile.
// Thread layout: 64 n-threads (4 consecutive n each, LDG.128) x 4 m-groups
// (8 m each, as 4 f32x2 pairs). 16 FFMA2 per k per thread.
// ---------------------------------------------------------------------------
__global__ __launch_bounds__(256, 2)
void gemm0_kernel(const float* __restrict__ x, const float* __restrict__ W0) {
    __shared__ float gs[KT][34];   // [kk][m], pad 34 -> 2-way store conflicts only

    const int tid  = threadIdx.x;
    const int nq   = tid & 63;
    const int mg   = tid >> 6;
    const int n0   = nq * 4;
    const int m0   = mg * 8;
    const int lane = tid & 31;
    const int wrp  = tid >> 5;
    const long k0  = (long)blockIdx.x * KC;

    unsigned long long acc[4][4];
#pragma unroll
    for (int p = 0; p < 4; p++)
#pragma unroll
        for (int j = 0; j < 4; j++) acc[p][j] = 0ull;

    for (int tile = 0; tile < KC / KT; ++tile) {
        const long kt = k0 + (long)tile * KT;
        // load g tile: 32 rows (m) x 32 cols (kk), coalesced per row
#pragma unroll
        for (int i = 0; i < 4; i++) {
            const int m = wrp * 4 + i;
            gs[lane][m] = x[(long)m * K_DIM + kt + lane];
        }
        __syncthreads();
#pragma unroll
        for (int kk = 0; kk < KT; ++kk) {
            const float4 wv = *(const float4*)(W0 + (kt + kk) * (long)N_DIM + n0);
            const unsigned long long ga = *(const unsigned long long*)&gs[kk][m0];
            const unsigned long long gb = *(const unsigned long long*)&gs[kk][m0 + 2];
            const unsigned long long gc = *(const unsigned long long*)&gs[kk][m0 + 4];
            const unsigned long long gd = *(const unsigned long long*)&gs[kk][m0 + 6];
            const unsigned long long w0r = pack2(wv.x, wv.x);
            const unsigned long long w1r = pack2(wv.y, wv.y);
            const unsigned long long w2r = pack2(wv.z, wv.z);
            const unsigned long long w3r = pack2(wv.w, wv.w);
            ffma2(acc[0][0], ga, w0r); ffma2(acc[0][1], ga, w1r);
            ffma2(acc[0][2], ga, w2r); ffma2(acc[0][3], ga, w3r);
            ffma2(acc[1][0], gb, w0r); ffma2(acc[1][1], gb, w1r);
            ffma2(acc[1][2], gb, w2r); ffma2(acc[1][3], gb, w3r);
            ffma2(acc[2][0], gc, w0r); ffma2(acc[2][1], gc, w1r);
            ffma2(acc[2][2], gc, w2r); ffma2(acc[2][3], gc, w3r);
            ffma2(acc[3][0], gd, w0r); ffma2(acc[3][1], gd, w1r);
            ffma2(acc[3][2], gd, w2r); ffma2(acc[3][3], gd, w3r);
        }
        __syncthreads();
    }

    float* pout = g_partial + (long)blockIdx.x * (M_DIM * N_DIM);
#pragma unroll
    for (int p = 0; p < 4; p++) {
        float lo[4], hi[4];
#pragma unroll
        for (int j = 0; j < 4; j++) unpack2(acc[p][j], lo[j], hi[j]);
        float4 r0 = make_float4(lo[0], lo[1], lo[2], lo[3]);
        float4 r1 = make_float4(hi[0], hi[1], hi[2], hi[3]);
        *(float4*)(pout + (m0 + 2 * p) * N_DIM + n0)     = r0;
        *(float4*)(pout + (m0 + 2 * p + 1) * N_DIM + n0) = r1;
    }
}

// ---------------------------------------------------------------------------
// K2: per-row reduce of partials (fixed order -> deterministic) + b0 + ELU,
// then h1 = ELU(h @ W1 + b1) for the same row m (row-local, so fused).
// ---------------------------------------------------------------------------
__global__ __launch_bounds__(256)
void mlp1_kernel(const float* __restrict__ b0, const float* __restrict__ W1,
                 const float* __restrict__ b1) {
    __shared__ float hs[256];
    const int m = blockIdx.x;
    const int n = threadIdx.x;

    float s = b0[n];
    const float* p = g_partial + m * N_DIM + n;
#pragma unroll 8
    for (int i = 0; i < SPLIT; i++) s += p[(long)i * (M_DIM * N_DIM)];
    hs[n] = elu(s);
    __syncthreads();

    float a = b1[n];
#pragma unroll 8
    for (int k = 0; k < 256; k++) a += hs[k] * W1[k * 256 + n];
    g_h1[m * 256 + n] = elu(a);
}

// ---------------------------------------------------------------------------
// K3: logits = h1 @ W2 + b2, softmax over E=4 (groups of 4 lanes via shfl).
// ---------------------------------------------------------------------------
__global__ void softmax_kernel(const float* __restrict__ W2,
                               const float* __restrict__ b2) {
    const int tid = threadIdx.x;   // 128 threads: (m, e)
    const int m = tid >> 2;
    const int e = tid & 3;
    float a = b2[e];
#pragma unroll 8
    for (int k = 0; k < 256; k++) a += g_h1[m * 256 + k] * W2[k * 4 + e];
    float mx = a;
    mx = fmaxf(mx, __shfl_xor_sync(0xffffffffu, mx, 1));
    mx = fmaxf(mx, __shfl_xor_sync(0xffffffffu, mx, 2));
    float ex = expf(a - mx);
    float sm = ex;
    sm += __shfl_xor_sync(0xffffffffu, sm, 1);
    sm += __shfl_xor_sync(0xffffffffu, sm, 2);
    g_w[m * 4 + e] = ex / sm;
}

// ---------------------------------------------------------------------------
// K4: per (t, n) block: AS = sum_e w[n,e] * A[e,t]  (25x25 in smem),
// then out[n, c, t, :] = x[n, c, t, :] @ AS for c = 0..63.
// ---------------------------------------------------------------------------
__global__ __launch_bounds__(256)
void gconv_kernel(const float* __restrict__ x, const float* __restrict__ A,
                  float* __restrict__ out) {
    __shared__ float AS[625];     // v*25 + w
    __shared__ float xs[1600];    // c*25 + v
    const int t = blockIdx.x;
    const int n = blockIdx.y;
    const int tid = threadIdx.x;

    const float w0 = g_w[n * 4 + 0];
    const float w1 = g_w[n * 4 + 1];
    const float w2 = g_w[n * 4 + 2];
    const float w3 = g_w[n * 4 + 3];

    const float* At = A + (long)t * 625;          // A[e,t,v,w] @ (e*128+t)*625
    for (int i = tid; i < 625; i += 256) {
        AS[i] = w0 * At[i]
              + w1 * At[1 * 128 * 625 + i]
              + w2 * At[2 * 128 * 625 + i]
              + w3 * At[3 * 128 * 625 + i];
    }

    const float* xb = x + (long)n * 204800 + t * 25;   // x[n, c, t, v]
    for (int i = tid; i < 1600; i += 256) {
        const int c = i / 25;
        const int v = i - c * 25;
        xs[i] = xb[(long)c * 3200 + v];
    }
    __syncthreads();

    float* ob = out + (long)n * 204800 + t * 25;
    for (int o = tid; o < 1600; o += 256) {
        const int c = o / 25;
        const int w = o - c * 25;
        float s = 0.0f;
#pragma unroll
        for (int v = 0; v < 25; v++) s += xs[c * 25 + v] * AS[v * 25 + w];
        ob[(long)c * 3200 + w] = s;
    }
}

// ---------------------------------------------------------------------------
extern "C" void kernel_launch(void* const* d_in, const int* in_sizes, int n_in,
                              void* d_out, int out_size) {
    const float* x  = (const float*)d_in[0];
    const float* W0 = (const float*)d_in[1];
    const float* b0 = (const float*)d_in[2];
    const float* W1 = (const float*)d_in[3];
    const float* b1 = (const float*)d_in[4];
    const float* W2 = (const float*)d_in[5];
    const float* b2 = (const float*)d_in[6];
    const float* A  = (const float*)d_in[7];
    float* out = (float*)d_out;

    gemm0_kernel<<<SPLIT, 256>>>(x, W0);
    mlp1_kernel<<<M_DIM, 256>>>(b0, W1, b1);
    softmax_kernel<<<1, 128>>>(W2, b2);
    gconv_kernel<<<dim3(128, 32), 256>>>(x, A, out);
}